// round 6
// baseline (speedup 1.0000x reference)
#include <cuda_runtime.h>
#include <cuda_bf16.h>
#include <cstdint>
#include <cstddef>

#define N_U 100000
#define N_I 50000
#define DD  64
#define QQ  5
#define NNZ_E 1000000
#define BB  512

typedef unsigned long long ull;

// ------------------------- scratch (device globals) -------------------------
__device__ __align__(16) float g_Z[(size_t)(N_U + N_I) * DD];    // Zu1, Zi1
__device__ __align__(16) float g_Ef[(size_t)(N_U + N_I) * DD];   // Euf, Eif (final E, aligned)
__device__ __align__(16) float g_small[2304];  // Mu(320) Mi(320) su(512) si(1024) sc(8)
__device__ __align__(16) float g_G[3 * BB * DD];   // Gu(512) + Gi(1024) rows, x5-folded

#define OFF_MU 0
#define OFF_MI 320
#define OFF_SU 640
#define OFF_SI 1152
#define OFF_SC 2176

// ------------------------------ helpers -------------------------------------
__device__ __forceinline__ ull ffma2(ull a, ull b, ull c) {
    ull d;
    asm("fma.rn.f32x2 %0, %1, %2, %3;" : "=l"(d) : "l"(a), "l"(b), "l"(c));
    return d;
}
__device__ __forceinline__ ull pack_dup(float a) {
    ull r; unsigned u = __float_as_uint(a);
    asm("mov.b64 %0, {%1, %1};" : "=l"(r) : "r"(u));
    return r;
}
__device__ __forceinline__ float fast_exp(float x) {
    if (fabsf(x) > 1.0f) return __expf(x);   // cold path; analytic |x| << 1
    float r = 1.9841270e-04f;
    r = fmaf(r, x, 1.3888889e-03f);
    r = fmaf(r, x, 8.3333333e-03f);
    r = fmaf(r, x, 4.1666667e-02f);
    r = fmaf(r, x, 1.6666667e-01f);
    r = fmaf(r, x, 0.5f);
    r = fmaf(r, x, 1.0f);
    r = fmaf(r, x, 1.0f);
    return r;
}
__device__ __forceinline__ float warp_sum(float v) {
    #pragma unroll
    for (int o = 16; o; o >>= 1) v += __shfl_xor_sync(0xffffffffu, v, o);
    return v;
}

// --------------------------------- SpMM --------------------------------------
// both directions in one launch; 4 edges/thread, front-batched gathers (MLP=4)
__global__ void spmm_dual(const float* __restrict__ vals,
                          const int* __restrict__ rows,
                          const int* __restrict__ cols,
                          const float* __restrict__ Xu,
                          const float* __restrict__ Xi,
                          float* __restrict__ Yu,
                          float* __restrict__ Yi) {
    const int half = gridDim.x >> 1;
    const bool dirU = blockIdx.x < half;
    const int bid = dirU ? blockIdx.x : blockIdx.x - half;
    const int t = bid * blockDim.x + threadIdx.x;
    const int e = t >> 4, lane = t & 15;
    const int E4 = NNZ_E / 4;
    if (e >= E4) return;
    const int* src = dirU ? cols : rows;
    const int* dst = dirU ? rows : cols;
    const float* X = dirU ? Xi : Xu;
    float* Y = dirU ? Yu : Yi;

    int e0 = e, e1 = e + E4, e2 = e + 2 * E4, e3 = e + 3 * E4;
    float v0 = __ldg(vals + e0), v1 = __ldg(vals + e1);
    float v2 = __ldg(vals + e2), v3 = __ldg(vals + e3);
    int c0 = __ldg(src + e0), c1 = __ldg(src + e1);
    int c2 = __ldg(src + e2), c3 = __ldg(src + e3);
    int r0 = __ldg(dst + e0), r1 = __ldg(dst + e1);
    int r2 = __ldg(dst + e2), r3 = __ldg(dst + e3);
    float4 x0 = ((const float4*)(X + (size_t)c0 * DD))[lane];
    float4 x1 = ((const float4*)(X + (size_t)c1 * DD))[lane];
    float4 x2 = ((const float4*)(X + (size_t)c2 * DD))[lane];
    float4 x3 = ((const float4*)(X + (size_t)c3 * DD))[lane];
    atomicAdd(((float4*)(Y + (size_t)r0 * DD)) + lane,
              make_float4(v0 * x0.x, v0 * x0.y, v0 * x0.z, v0 * x0.w));
    atomicAdd(((float4*)(Y + (size_t)r1 * DD)) + lane,
              make_float4(v1 * x1.x, v1 * x1.y, v1 * x1.z, v1 * x1.w));
    atomicAdd(((float4*)(Y + (size_t)r2 * DD)) + lane,
              make_float4(v2 * x2.x, v2 * x2.y, v2 * x2.z, v2 * x2.w));
    atomicAdd(((float4*)(Y + (size_t)r3 * DD)) + lane,
              make_float4(v3 * x3.x, v3 * x3.y, v3 * x3.z, v3 * x3.w));
}

// ------------------------- prep: Ef = E0+Z1 ; M, reg -------------------------
__global__ void prep_kernel(const float* __restrict__ E0,
                            const float* __restrict__ Z1,
                            const float* __restrict__ P, int n_rows,
                            float* __restrict__ Ef,
                            float* __restrict__ Macc,
                            float* __restrict__ regAcc) {
    int d = threadIdx.x & 63;
    int grp = threadIdx.x >> 6;                 // 0..3
    float m0 = 0, m1 = 0, m2 = 0, m3 = 0, m4 = 0, racc = 0;
    for (int r = blockIdx.x * 4 + grp; r < n_rows; r += gridDim.x * 4) {
        size_t off = (size_t)r * DD + d;
        float e0 = E0[off];
        float t  = e0 + Z1[off];
        Ef[off] = t;
        racc = fmaf(e0, e0, racc);
        m0 = fmaf(__ldg(P + r), t, m0);
        m1 = fmaf(__ldg(P + (size_t)n_rows + r), t, m1);
        m2 = fmaf(__ldg(P + 2 * (size_t)n_rows + r), t, m2);
        m3 = fmaf(__ldg(P + 3 * (size_t)n_rows + r), t, m3);
        m4 = fmaf(__ldg(P + 4 * (size_t)n_rows + r), t, m4);
    }
    __shared__ float sm[4][QQ][DD];
    sm[grp][0][d] = m0; sm[grp][1][d] = m1; sm[grp][2][d] = m2;
    sm[grp][3][d] = m3; sm[grp][4][d] = m4;
    __syncthreads();
    if (grp == 0) {
        #pragma unroll
        for (int q = 0; q < QQ; q++)
            atomicAdd(&Macc[q * DD + d],
                      sm[0][q][d] + sm[1][q][d] + sm[2][q][d] + sm[3][q][d]);
    }
    racc = warp_sum(racc);
    if ((threadIdx.x & 31) == 0) atomicAdd(regAcc, racc);
}

// -------------------- copy aligned Ef -> misaligned d_out --------------------
__global__ void copyout_kernel(const float* __restrict__ Ef,
                               float* __restrict__ Eout, size_t n4) {
    size_t i = (size_t)blockIdx.x * blockDim.x + threadIdx.x;
    if (i >= n4) return;
    float4 v = ((const float4*)Ef)[i];
    float* o = Eout + i * 4;
    o[0] = v.x; o[1] = v.y; o[2] = v.z; o[3] = v.w;
}

// ------------------------------ G selection ----------------------------------
__global__ void gsel_kernel(const int* __restrict__ uids,
                            const int* __restrict__ pos,
                            const int* __restrict__ neg,
                            const float* __restrict__ Eu0,
                            const float* __restrict__ Ei0,
                            const float* __restrict__ mu_s,
                            const float* __restrict__ mi_s,
                            const float* __restrict__ Mu,
                            const float* __restrict__ Mi,
                            float* __restrict__ G) {
    int b = blockIdx.x, d = threadIdx.x;
    const float* E0; const float* ms; const float* M; int id;
    if (b < 512)       { E0 = Eu0; ms = mu_s; M = Mu; id = uids[b]; }
    else if (b < 1024) { E0 = Ei0; ms = mi_s; M = Mi; id = pos[b - 512]; }
    else               { E0 = Ei0; ms = mi_s; M = Mi; id = neg[b - 1024]; }
    float v = E0[(size_t)id * DD + d];
    #pragma unroll
    for (int q = 0; q < QQ; q++)
        v = fmaf(ms[(size_t)id * QQ + q], M[q * DD + d], v);
    G[b * DD + d] = 5.0f * v;
}

// ---------------- SIMT logits: 64x128 tiled GEMM + exp + row-sum -------------
// smem: Gd (dup f32x2) [64k][64m] = 32KB ; Ep (col pairs (n, n+64)) [64k][64] = 32KB
// 256 threads, 4m x 8n per thread, 3 CTAs/SM.
#define SMEM_LG (64 * 1024)
__global__ __launch_bounds__(256, 3)
void logits_simt(const float* __restrict__ G, int Mtiles,
                 const float* __restrict__ Ef, int N,
                 float* __restrict__ S) {
    extern __shared__ char smc[];
    ull* Gd = (ull*)smc;                 // [k*64 + m], value duplicated
    ull* Ep = (ull*)(smc + 32768);       // [k*64 + c], lo=E[n0+c], hi=E[n0+c+64]
    const int tid = threadIdx.x;
    const int mt = blockIdx.x % Mtiles;
    const long n0 = (long)(blockIdx.x / Mtiles) * 128;

    // G tile: 64 rows x 64 k
    #pragma unroll
    for (int it = 0; it < 4; it++) {
        int idx = it * 256 + tid;        // 0..1023
        int row = idx >> 4;              // 0..63
        int kc  = idx & 15;              // float4 chunk
        float4 g = *(const float4*)(G + ((size_t)(mt * 64 + row)) * DD + kc * 4);
        Gd[(kc * 4 + 0) * 64 + row] = pack_dup(g.x);
        Gd[(kc * 4 + 1) * 64 + row] = pack_dup(g.y);
        Gd[(kc * 4 + 2) * 64 + row] = pack_dup(g.z);
        Gd[(kc * 4 + 3) * 64 + row] = pack_dup(g.w);
    }
    // E tile: rows [n0, n0+128); row<64 -> lo slot, row>=64 -> hi slot
    float* Epf = (float*)Ep;
    #pragma unroll
    for (int it = 0; it < 8; it++) {
        int idx = it * 256 + tid;        // 0..2047
        int row = idx >> 4;              // 0..127
        int kc  = idx & 15;
        long n = n0 + row;
        float4 e = make_float4(0.f, 0.f, 0.f, 0.f);
        if (n < N) e = *(const float4*)(Ef + n * DD + kc * 4);
        int c = row & 63, hi = row >> 6;
        Epf[((kc * 4 + 0) * 64 + c) * 2 + hi] = e.x;
        Epf[((kc * 4 + 1) * 64 + c) * 2 + hi] = e.y;
        Epf[((kc * 4 + 2) * 64 + c) * 2 + hi] = e.z;
        Epf[((kc * 4 + 3) * 64 + c) * 2 + hi] = e.w;
    }
    __syncthreads();

    const int tx = tid & 15, ty = tid >> 4;
    ull acc[4][4];
    #pragma unroll
    for (int i = 0; i < 4; i++)
        #pragma unroll
        for (int j = 0; j < 4; j++) acc[i][j] = 0ull;

    const ull* gp = Gd + ty * 4;          // +64 per k
    const ull* ep = Ep + tx * 4;          // +64 per k
    #pragma unroll 4
    for (int k = 0; k < 64; k++) {
        ulonglong2 b01 = *(const ulonglong2*)(ep + 0);
        ulonglong2 b23 = *(const ulonglong2*)(ep + 2);
        ulonglong2 g01 = *(const ulonglong2*)(gp + 0);
        ulonglong2 g23 = *(const ulonglong2*)(gp + 2);
        ull g[4] = { g01.x, g01.y, g23.x, g23.y };
        ull b[4] = { b01.x, b01.y, b23.x, b23.y };
        #pragma unroll
        for (int i = 0; i < 4; i++) {
            acc[i][0] = ffma2(g[i], b[0], acc[i][0]);
            acc[i][1] = ffma2(g[i], b[1], acc[i][1]);
            acc[i][2] = ffma2(g[i], b[2], acc[i][2]);
            acc[i][3] = ffma2(g[i], b[3], acc[i][3]);
        }
        gp += 64; ep += 64;
    }

    // epilogue: exp + row-sum (logits already x5 via G)
    bool full = (n0 + 128 <= N);
    #pragma unroll
    for (int i = 0; i < 4; i++) {
        float s = 0.f;
        #pragma unroll
        for (int j = 0; j < 4; j++) {
            float lo = __uint_as_float((unsigned)acc[i][j]);
            float hi = __uint_as_float((unsigned)(acc[i][j] >> 32));
            if (full) {
                s += fast_exp(lo) + fast_exp(hi);
            } else {
                long n = n0 + tx * 4 + j;
                if (n < N)      s += fast_exp(lo);
                if (n + 64 < N) s += fast_exp(hi);
            }
        }
        s += __shfl_xor_sync(0xffffffffu, s, 1);
        s += __shfl_xor_sync(0xffffffffu, s, 2);
        s += __shfl_xor_sync(0xffffffffu, s, 4);
        s += __shfl_xor_sync(0xffffffffu, s, 8);
        if (tx == 0) atomicAdd(&S[mt * 64 + ty * 4 + i], s);
    }
}

// -------------------- pos / BPR / extra-loss (warp-per-task) -----------------
__global__ void small_loss_kernel(const int* __restrict__ uids,
                                  const int* __restrict__ pos,
                                  const int* __restrict__ neg,
                                  const float* __restrict__ Eu,
                                  const float* __restrict__ Ei,
                                  const float* __restrict__ Gu,
                                  const float* __restrict__ Gi,
                                  const int* __restrict__ unpop,
                                  const int* __restrict__ popi,
                                  float* __restrict__ sc) {
    int gtid = blockIdx.x * blockDim.x + threadIdx.x;
    int wid = gtid >> 5, lane = gtid & 31;
    if (wid < 512) {                       // pos_u
        int b = wid, u = uids[b];
        float s = Gu[b * DD + lane] * Eu[(size_t)u * DD + lane]
                + Gu[b * DD + 32 + lane] * Eu[(size_t)u * DD + 32 + lane];
        s = warp_sum(s);
        if (lane == 0) atomicAdd(&sc[1], fminf(fmaxf(s, -5.0f), 5.0f));
    } else if (wid < 1536) {               // pos_i
        int b = wid - 512;
        int id = (b < 512) ? pos[b] : neg[b - 512];
        float s = Gi[b * DD + lane] * Ei[(size_t)id * DD + lane]
                + Gi[b * DD + 32 + lane] * Ei[(size_t)id * DD + 32 + lane];
        s = warp_sum(s);
        if (lane == 0) atomicAdd(&sc[2], fminf(fmaxf(s, -5.0f), 5.0f));
    } else if (wid < 2048) {               // BPR
        int b = wid - 1536, u = uids[b], p = pos[b], nn = neg[b];
        float eu0 = Eu[(size_t)u * DD + lane], eu1 = Eu[(size_t)u * DD + 32 + lane];
        float sp = eu0 * Ei[(size_t)p * DD + lane]  + eu1 * Ei[(size_t)p * DD + 32 + lane];
        float sn = eu0 * Ei[(size_t)nn * DD + lane] + eu1 * Ei[(size_t)nn * DD + 32 + lane];
        sp = warp_sum(sp);
        sn = warp_sum(sn);
        if (lane == 0) {
            float x = sp - sn;
            float t = (x > 0.f) ? log1pf(expf(-x)) : (-x + log1pf(expf(x)));
            atomicAdd(&sc[3], t);
        }
    } else {                               // extra-loss pairs
        int p = wid - 2048;
        if (p >= 64 * 8 * 32) return;
        int ig = p >> 8, rem = p & 255, ui = rem >> 5, pi = rem & 31;
        int a = unpop[ig * 8 + ui];
        int c = popi[ig * 32 + pi];
        float d0 = Ei[(size_t)a * DD + lane] - Ei[(size_t)c * DD + lane];
        float d1 = Ei[(size_t)a * DD + 32 + lane] - Ei[(size_t)c * DD + 32 + lane];
        float s = warp_sum(d0 * d0 + d1 * d1);
        if (lane == 0) atomicAdd(&sc[4], sqrtf(s));
    }
}

// ------------------------------ weight L2 reg --------------------------------
__global__ void reg_w_kernel(const float* __restrict__ W1,
                             const float* __restrict__ b1,
                             const float* __restrict__ W2,
                             const float* __restrict__ b2,
                             float* __restrict__ acc) {
    int t = blockIdx.x * blockDim.x + threadIdx.x;
    int total = gridDim.x * blockDim.x;
    float s = 0.f;
    for (int i = t; i < 768 * 64; i += total) {
        float a = W1[i]; s = fmaf(a, a, s);
        float c = W2[i]; s = fmaf(c, c, s);
    }
    if (t < 64) {
        float a = b1[t]; s = fmaf(a, a, s);
        float c = b2[t]; s = fmaf(c, c, s);
    }
    s = warp_sum(s);
    if ((threadIdx.x & 31) == 0) atomicAdd(acc, s);
}

// -------------------------------- finalize -----------------------------------
__global__ void finalize_kernel(const float* __restrict__ su,
                                const float* __restrict__ si,
                                const float* __restrict__ sc,
                                float* __restrict__ out) {
    __shared__ float s_lu[16], s_li[16];
    int tid = threadIdx.x;   // 512 threads
    float lu = logf(su[tid] + 1e-8f);
    float li = logf(si[tid] + 1e-8f) + logf(si[tid + 512] + 1e-8f);
    lu = warp_sum(lu);
    li = warp_sum(li);
    if ((tid & 31) == 0) { s_lu[tid >> 5] = lu; s_li[tid >> 5] = li; }
    __syncthreads();
    if (tid == 0) {
        float LU = 0.f, LI = 0.f;
        #pragma unroll
        for (int w = 0; w < 16; w++) { LU += s_lu[w]; LI += s_li[w]; }
        float neg_score = LU / 512.f + LI / 1024.f;
        float pos_score = sc[1] / 512.f + sc[2] / 1024.f;
        float loss_s = -pos_score + neg_score;
        float loss_r = sc[3] / 512.f;
        float loss_reg = 1e-7f * sc[0];
        float extra = sc[4] * (1.f / 32.f);
        float loss = loss_r + 0.2f * loss_s + loss_reg + 0.01f * extra;
        out[0] = loss;
        out[1] = loss_r;
        out[2] = 0.2f * loss_s;
    }
}

// ------------------------------- launcher ------------------------------------
extern "C" void kernel_launch(void* const* d_in, const int* in_sizes, int n_in,
                              void* d_out, int out_size) {
    const int*   uids     = (const int*)d_in[0];
    const int*   pos      = (const int*)d_in[1];
    const int*   neg      = (const int*)d_in[2];
    const int*   adj_rows = (const int*)d_in[3];
    const int*   adj_cols = (const int*)d_in[4];
    const float* adj_vals = (const float*)d_in[5];
    const float* E_u_0    = (const float*)d_in[6];
    const float* E_i_0    = (const float*)d_in[7];
    const float* u_mul_s  = (const float*)d_in[8];
    const float* vt       = (const float*)d_in[9];
    const float* v_mul_s  = (const float*)d_in[10];
    const float* ut       = (const float*)d_in[11];
    const float* W_api    = (const float*)d_in[12];
    const float* b_api    = (const float*)d_in[13];
    const float* W_mashup = (const float*)d_in[14];
    const float* b_mashup = (const float*)d_in[15];
    const float* pos_api  = (const float*)d_in[16];
    const float* neg_api  = (const float*)d_in[17];
    const float* mashup   = (const float*)d_in[18];
    const int*   unpop    = (const int*)d_in[19];
    const int*   popi     = (const int*)d_in[20];

    float* out = (float*)d_out;
    const size_t EMB = (size_t)512 * 768;
    float* out_mashup = out + 3;
    float* out_posapi = out + 3 + EMB;
    float* out_negapi = out + 3 + 2 * EMB;
    float* Eu_out = out + 3 + 3 * EMB;   // Ei_out contiguous after

    float *Zb, *Efb, *Sm, *G;
    cudaGetSymbolAddress((void**)&Zb,  g_Z);
    cudaGetSymbolAddress((void**)&Efb, g_Ef);
    cudaGetSymbolAddress((void**)&Sm,  g_small);
    cudaGetSymbolAddress((void**)&G,   g_G);

    float* Zu1 = Zb;
    float* Zi1 = Zu1 + (size_t)N_U * DD;
    float* Euf = Efb;
    float* Eif = Euf + (size_t)N_U * DD;
    float* Mu = Sm + OFF_MU;
    float* Mi = Sm + OFF_MI;
    float* su = Sm + OFF_SU;
    float* si = Sm + OFF_SI;
    float* sc = Sm + OFF_SC;
    float* Gu = G;
    float* Gi = G + (size_t)BB * DD;

    cudaMemsetAsync(Zb, 0, (size_t)(N_U + N_I) * DD * 4);
    cudaMemsetAsync(Sm, 0, 2304 * 4);

    cudaMemcpyAsync(out_mashup, mashup, EMB * 4, cudaMemcpyDeviceToDevice);
    cudaMemcpyAsync(out_posapi, pos_api, EMB * 4, cudaMemcpyDeviceToDevice);
    cudaMemcpyAsync(out_negapi, neg_api, EMB * 4, cudaMemcpyDeviceToDevice);

    const int spmm_blocks = 2 * (((NNZ_E / 4) * 16 + 255) / 256);
    spmm_dual<<<spmm_blocks, 256>>>(adj_vals, adj_rows, adj_cols,
                                    E_u_0, E_i_0, Zu1, Zi1);
    prep_kernel<<<2048, 256>>>(E_u_0, Zu1, ut, N_U, Euf, Mi, sc);
    prep_kernel<<<1024, 256>>>(E_i_0, Zi1, vt, N_I, Eif, Mu, sc);
    spmm_dual<<<spmm_blocks, 256>>>(adj_vals, adj_rows, adj_cols,
                                    Zu1, Zi1, Euf, Eif);

    reg_w_kernel<<<64, 256>>>(W_api, b_api, W_mashup, b_mashup, sc);
    gsel_kernel<<<1536, 64>>>(uids, pos, neg, E_u_0, E_i_0,
                              u_mul_s, v_mul_s, Mu, Mi, G);

    cudaFuncSetAttribute(logits_simt,
                         cudaFuncAttributeMaxDynamicSharedMemorySize, SMEM_LG);
    const int ntu = (N_U + 127) / 128;   // 782
    const int nti = (N_I + 127) / 128;   // 391
    logits_simt<<<8 * ntu, 256, SMEM_LG>>>(Gu, 8, Euf, N_U, su);
    logits_simt<<<16 * nti, 256, SMEM_LG>>>(Gi, 16, Eif, N_I, si);

    small_loss_kernel<<<2304, 256>>>(uids, pos, neg, Euf, Eif, Gu, Gi,
                                     unpop, popi, sc);

    const size_t n4 = (size_t)(N_U + N_I) * DD / 4;
    copyout_kernel<<<(int)((n4 + 255) / 256), 256>>>(Efb, Eu_out, n4);

    finalize_kernel<<<1, 512>>>(su, si, sc, out);
}

// round 7
// speedup vs baseline: 1.6319x; 1.6319x over previous
#include <cuda_runtime.h>
#include <cuda_bf16.h>
#include <cstdint>
#include <cstddef>

#define N_U 100000
#define N_I 50000
#define DD  64
#define QQ  5
#define NNZ_E 1000000
#define BB  512

typedef unsigned long long ull;

// ------------------------- scratch (device globals) -------------------------
__device__ __align__(16) float g_Z[(size_t)(N_U + N_I) * DD];    // Zu1, Zi1
__device__ __align__(16) float g_Ef[(size_t)(N_U + N_I) * DD];   // Euf, Eif (final E, aligned)
__device__ __align__(16) float g_small[2304];  // Mu(320) Mi(320) su(512) si(1024) sc(8)
__device__ __align__(16) float g_G[3 * BB * DD];   // Gu(512) + Gi(1024) rows, x5-folded

#define OFF_MU 0
#define OFF_MI 320
#define OFF_SU 640
#define OFF_SI 1152
#define OFF_SC 2176

// ------------------------------ helpers -------------------------------------
__device__ __forceinline__ ull ffma2(ull a, ull b, ull c) {
    ull d;
    asm("fma.rn.f32x2 %0, %1, %2, %3;" : "=l"(d) : "l"(a), "l"(b), "l"(c));
    return d;
}
__device__ __forceinline__ ull pack_dup(float a) {
    ull r; unsigned u = __float_as_uint(a);
    asm("mov.b64 %0, {%1, %1};" : "=l"(r) : "r"(u));
    return r;
}
__device__ __forceinline__ float warp_sum(float v) {
    #pragma unroll
    for (int o = 16; o; o >>= 1) v += __shfl_xor_sync(0xffffffffu, v, o);
    return v;
}

// --------------------------------- SpMM --------------------------------------
// both directions in one launch; 4 edges/thread, front-batched gathers (MLP=4)
__global__ void spmm_dual(const float* __restrict__ vals,
                          const int* __restrict__ rows,
                          const int* __restrict__ cols,
                          const float* __restrict__ Xu,
                          const float* __restrict__ Xi,
                          float* __restrict__ Yu,
                          float* __restrict__ Yi) {
    const int half = gridDim.x >> 1;
    const bool dirU = blockIdx.x < half;
    const int bid = dirU ? blockIdx.x : blockIdx.x - half;
    const int t = bid * blockDim.x + threadIdx.x;
    const int e = t >> 4, lane = t & 15;
    const int E4 = NNZ_E / 4;
    if (e >= E4) return;
    const int* src = dirU ? cols : rows;
    const int* dst = dirU ? rows : cols;
    const float* X = dirU ? Xi : Xu;
    float* Y = dirU ? Yu : Yi;

    int e0 = e, e1 = e + E4, e2 = e + 2 * E4, e3 = e + 3 * E4;
    float v0 = __ldg(vals + e0), v1 = __ldg(vals + e1);
    float v2 = __ldg(vals + e2), v3 = __ldg(vals + e3);
    int c0 = __ldg(src + e0), c1 = __ldg(src + e1);
    int c2 = __ldg(src + e2), c3 = __ldg(src + e3);
    int r0 = __ldg(dst + e0), r1 = __ldg(dst + e1);
    int r2 = __ldg(dst + e2), r3 = __ldg(dst + e3);
    float4 x0 = ((const float4*)(X + (size_t)c0 * DD))[lane];
    float4 x1 = ((const float4*)(X + (size_t)c1 * DD))[lane];
    float4 x2 = ((const float4*)(X + (size_t)c2 * DD))[lane];
    float4 x3 = ((const float4*)(X + (size_t)c3 * DD))[lane];
    atomicAdd(((float4*)(Y + (size_t)r0 * DD)) + lane,
              make_float4(v0 * x0.x, v0 * x0.y, v0 * x0.z, v0 * x0.w));
    atomicAdd(((float4*)(Y + (size_t)r1 * DD)) + lane,
              make_float4(v1 * x1.x, v1 * x1.y, v1 * x1.z, v1 * x1.w));
    atomicAdd(((float4*)(Y + (size_t)r2 * DD)) + lane,
              make_float4(v2 * x2.x, v2 * x2.y, v2 * x2.z, v2 * x2.w));
    atomicAdd(((float4*)(Y + (size_t)r3 * DD)) + lane,
              make_float4(v3 * x3.x, v3 * x3.y, v3 * x3.z, v3 * x3.w));
}

// ------------------------- prep: Ef = E0+Z1 ; M, reg -------------------------
__global__ void prep_kernel(const float* __restrict__ E0,
                            const float* __restrict__ Z1,
                            const float* __restrict__ P, int n_rows,
                            float* __restrict__ Ef,
                            float* __restrict__ Macc,
                            float* __restrict__ regAcc) {
    int d = threadIdx.x & 63;
    int grp = threadIdx.x >> 6;                 // 0..3
    float m0 = 0, m1 = 0, m2 = 0, m3 = 0, m4 = 0, racc = 0;
    for (int r = blockIdx.x * 4 + grp; r < n_rows; r += gridDim.x * 4) {
        size_t off = (size_t)r * DD + d;
        float e0 = E0[off];
        float t  = e0 + Z1[off];
        Ef[off] = t;
        racc = fmaf(e0, e0, racc);
        m0 = fmaf(__ldg(P + r), t, m0);
        m1 = fmaf(__ldg(P + (size_t)n_rows + r), t, m1);
        m2 = fmaf(__ldg(P + 2 * (size_t)n_rows + r), t, m2);
        m3 = fmaf(__ldg(P + 3 * (size_t)n_rows + r), t, m3);
        m4 = fmaf(__ldg(P + 4 * (size_t)n_rows + r), t, m4);
    }
    __shared__ float sm[4][QQ][DD];
    sm[grp][0][d] = m0; sm[grp][1][d] = m1; sm[grp][2][d] = m2;
    sm[grp][3][d] = m3; sm[grp][4][d] = m4;
    __syncthreads();
    if (grp == 0) {
        #pragma unroll
        for (int q = 0; q < QQ; q++)
            atomicAdd(&Macc[q * DD + d],
                      sm[0][q][d] + sm[1][q][d] + sm[2][q][d] + sm[3][q][d]);
    }
    racc = warp_sum(racc);
    if ((threadIdx.x & 31) == 0) atomicAdd(regAcc, racc);
}

// -------------------- copy aligned Ef -> misaligned d_out --------------------
__global__ void copyout_kernel(const float* __restrict__ Ef,
                               float* __restrict__ Eout, size_t n4) {
    size_t i = (size_t)blockIdx.x * blockDim.x + threadIdx.x;
    if (i >= n4) return;
    float4 v = ((const float4*)Ef)[i];
    float* o = Eout + i * 4;
    o[0] = v.x; o[1] = v.y; o[2] = v.z; o[3] = v.w;
}

// ------------------------------ G selection ----------------------------------
__global__ void gsel_kernel(const int* __restrict__ uids,
                            const int* __restrict__ pos,
                            const int* __restrict__ neg,
                            const float* __restrict__ Eu0,
                            const float* __restrict__ Ei0,
                            const float* __restrict__ mu_s,
                            const float* __restrict__ mi_s,
                            const float* __restrict__ Mu,
                            const float* __restrict__ Mi,
                            float* __restrict__ G) {
    int b = blockIdx.x, d = threadIdx.x;
    const float* E0; const float* ms; const float* M; int id;
    if (b < 512)       { E0 = Eu0; ms = mu_s; M = Mu; id = uids[b]; }
    else if (b < 1024) { E0 = Ei0; ms = mi_s; M = Mi; id = pos[b - 512]; }
    else               { E0 = Ei0; ms = mi_s; M = Mi; id = neg[b - 1024]; }
    float v = E0[(size_t)id * DD + d];
    #pragma unroll
    for (int q = 0; q < QQ; q++)
        v = fmaf(ms[(size_t)id * QQ + q], M[q * DD + d], v);
    G[b * DD + d] = 5.0f * v;
}

// ---------------- SIMT logits: 128x128 tiled GEMM + exp + row-sum ------------
// smem: Gd (dup f32x2) [64k][128m] = 64KB ; Ep (col pairs (n, n+64)) [64k][64] = 32KB
// R4-exact mainloop (conflict-free stride-16 LDS.64 b loads); epilogue = __expf.
#define SMEM_LG (96 * 1024)
__global__ __launch_bounds__(256, 2)
void logits_simt(const float* __restrict__ G, int Mtiles,
                 const float* __restrict__ Ef, int N,
                 float* __restrict__ S) {
    extern __shared__ char smc[];
    ull* Gd = (ull*)smc;                 // [k*128 + m], value duplicated
    ull* Ep = (ull*)(smc + 65536);       // [k*64 + c], lo=E[n0+c], hi=E[n0+c+64]
    const int tid = threadIdx.x;
    const int mt = blockIdx.x % Mtiles;
    const long n0 = (long)(blockIdx.x / Mtiles) * 128;

    #pragma unroll
    for (int it = 0; it < 8; it++) {
        int idx = it * 256 + tid;
        int kc = idx >> 7, row = idx & 127;
        float4 g = *(const float4*)(G + ((size_t)(mt * 128 + row)) * DD + kc * 4);
        Gd[(kc * 4 + 0) * 128 + row] = pack_dup(g.x);
        Gd[(kc * 4 + 1) * 128 + row] = pack_dup(g.y);
        Gd[(kc * 4 + 2) * 128 + row] = pack_dup(g.z);
        Gd[(kc * 4 + 3) * 128 + row] = pack_dup(g.w);
    }
    float* Epf = (float*)Ep;
    #pragma unroll
    for (int it = 0; it < 8; it++) {
        int idx = it * 256 + tid;
        int kc = idx >> 7, row = idx & 127;
        long n = n0 + row;
        float4 e = make_float4(0.f, 0.f, 0.f, 0.f);
        if (n < N) e = *(const float4*)(Ef + n * DD + kc * 4);
        int c = row & 63, hi = row >> 6;
        Epf[((kc * 4 + 0) * 64 + c) * 2 + hi] = e.x;
        Epf[((kc * 4 + 1) * 64 + c) * 2 + hi] = e.y;
        Epf[((kc * 4 + 2) * 64 + c) * 2 + hi] = e.z;
        Epf[((kc * 4 + 3) * 64 + c) * 2 + hi] = e.w;
    }
    __syncthreads();

    const int tx = tid & 15, ty = tid >> 4;
    ull acc[8][4];
    #pragma unroll
    for (int i = 0; i < 8; i++)
        #pragma unroll
        for (int j = 0; j < 4; j++) acc[i][j] = 0ull;

    const ull* gp = Gd + ty * 8;
    const ull* ep = Ep + tx;
    #pragma unroll 4
    for (int k = 0; k < 64; k++) {
        ull b0 = ep[0], b1 = ep[16], b2 = ep[32], b3 = ep[48];
        #pragma unroll
        for (int i = 0; i < 8; i++) {
            ull a = gp[i];
            acc[i][0] = ffma2(a, b0, acc[i][0]);
            acc[i][1] = ffma2(a, b1, acc[i][1]);
            acc[i][2] = ffma2(a, b2, acc[i][2]);
            acc[i][3] = ffma2(a, b3, acc[i][3]);
        }
        gp += 128; ep += 64;
    }

    // epilogue: exp (MUFU.EX2 via __expf) + row-sum (logits already x5 via G)
    bool full = (n0 + 128 <= N);
    #pragma unroll
    for (int i = 0; i < 8; i++) {
        float s = 0.f;
        #pragma unroll
        for (int j = 0; j < 4; j++) {
            float lo = __uint_as_float((unsigned)acc[i][j]);
            float hi = __uint_as_float((unsigned)(acc[i][j] >> 32));
            if (full) {
                s += __expf(lo) + __expf(hi);
            } else {
                long n = n0 + tx + 16 * j;
                if (n < N)      s += __expf(lo);
                if (n + 64 < N) s += __expf(hi);
            }
        }
        s += __shfl_xor_sync(0xffffffffu, s, 1);
        s += __shfl_xor_sync(0xffffffffu, s, 2);
        s += __shfl_xor_sync(0xffffffffu, s, 4);
        s += __shfl_xor_sync(0xffffffffu, s, 8);
        if (tx == 0) atomicAdd(&S[mt * 128 + ty * 8 + i], s);
    }
}

// -------------------- pos / BPR / extra-loss (warp-per-task) -----------------
__global__ void small_loss_kernel(const int* __restrict__ uids,
                                  const int* __restrict__ pos,
                                  const int* __restrict__ neg,
                                  const float* __restrict__ Eu,
                                  const float* __restrict__ Ei,
                                  const float* __restrict__ Gu,
                                  const float* __restrict__ Gi,
                                  const int* __restrict__ unpop,
                                  const int* __restrict__ popi,
                                  float* __restrict__ sc) {
    int gtid = blockIdx.x * blockDim.x + threadIdx.x;
    int wid = gtid >> 5, lane = gtid & 31;
    if (wid < 512) {                       // pos_u
        int b = wid, u = uids[b];
        float s = Gu[b * DD + lane] * Eu[(size_t)u * DD + lane]
                + Gu[b * DD + 32 + lane] * Eu[(size_t)u * DD + 32 + lane];
        s = warp_sum(s);
        if (lane == 0) atomicAdd(&sc[1], fminf(fmaxf(s, -5.0f), 5.0f));
    } else if (wid < 1536) {               // pos_i
        int b = wid - 512;
        int id = (b < 512) ? pos[b] : neg[b - 512];
        float s = Gi[b * DD + lane] * Ei[(size_t)id * DD + lane]
                + Gi[b * DD + 32 + lane] * Ei[(size_t)id * DD + 32 + lane];
        s = warp_sum(s);
        if (lane == 0) atomicAdd(&sc[2], fminf(fmaxf(s, -5.0f), 5.0f));
    } else if (wid < 2048) {               // BPR
        int b = wid - 1536, u = uids[b], p = pos[b], nn = neg[b];
        float eu0 = Eu[(size_t)u * DD + lane], eu1 = Eu[(size_t)u * DD + 32 + lane];
        float sp = eu0 * Ei[(size_t)p * DD + lane]  + eu1 * Ei[(size_t)p * DD + 32 + lane];
        float sn = eu0 * Ei[(size_t)nn * DD + lane] + eu1 * Ei[(size_t)nn * DD + 32 + lane];
        sp = warp_sum(sp);
        sn = warp_sum(sn);
        if (lane == 0) {
            float x = sp - sn;
            float t = (x > 0.f) ? log1pf(expf(-x)) : (-x + log1pf(expf(x)));
            atomicAdd(&sc[3], t);
        }
    } else {                               // extra-loss pairs
        int p = wid - 2048;
        if (p >= 64 * 8 * 32) return;
        int ig = p >> 8, rem = p & 255, ui = rem >> 5, pi = rem & 31;
        int a = unpop[ig * 8 + ui];
        int c = popi[ig * 32 + pi];
        float d0 = Ei[(size_t)a * DD + lane] - Ei[(size_t)c * DD + lane];
        float d1 = Ei[(size_t)a * DD + 32 + lane] - Ei[(size_t)c * DD + 32 + lane];
        float s = warp_sum(d0 * d0 + d1 * d1);
        if (lane == 0) atomicAdd(&sc[4], sqrtf(s));
    }
}

// ------------------------------ weight L2 reg --------------------------------
__global__ void reg_w_kernel(const float* __restrict__ W1,
                             const float* __restrict__ b1,
                             const float* __restrict__ W2,
                             const float* __restrict__ b2,
                             float* __restrict__ acc) {
    int t = blockIdx.x * blockDim.x + threadIdx.x;
    int total = gridDim.x * blockDim.x;
    float s = 0.f;
    for (int i = t; i < 768 * 64; i += total) {
        float a = W1[i]; s = fmaf(a, a, s);
        float c = W2[i]; s = fmaf(c, c, s);
    }
    if (t < 64) {
        float a = b1[t]; s = fmaf(a, a, s);
        float c = b2[t]; s = fmaf(c, c, s);
    }
    s = warp_sum(s);
    if ((threadIdx.x & 31) == 0) atomicAdd(acc, s);
}

// -------------------------------- finalize -----------------------------------
__global__ void finalize_kernel(const float* __restrict__ su,
                                const float* __restrict__ si,
                                const float* __restrict__ sc,
                                float* __restrict__ out) {
    __shared__ float s_lu[16], s_li[16];
    int tid = threadIdx.x;   // 512 threads
    float lu = logf(su[tid] + 1e-8f);
    float li = logf(si[tid] + 1e-8f) + logf(si[tid + 512] + 1e-8f);
    lu = warp_sum(lu);
    li = warp_sum(li);
    if ((tid & 31) == 0) { s_lu[tid >> 5] = lu; s_li[tid >> 5] = li; }
    __syncthreads();
    if (tid == 0) {
        float LU = 0.f, LI = 0.f;
        #pragma unroll
        for (int w = 0; w < 16; w++) { LU += s_lu[w]; LI += s_li[w]; }
        float neg_score = LU / 512.f + LI / 1024.f;
        float pos_score = sc[1] / 512.f + sc[2] / 1024.f;
        float loss_s = -pos_score + neg_score;
        float loss_r = sc[3] / 512.f;
        float loss_reg = 1e-7f * sc[0];
        float extra = sc[4] * (1.f / 32.f);
        float loss = loss_r + 0.2f * loss_s + loss_reg + 0.01f * extra;
        out[0] = loss;
        out[1] = loss_r;
        out[2] = 0.2f * loss_s;
    }
}

// ------------------------------- launcher ------------------------------------
extern "C" void kernel_launch(void* const* d_in, const int* in_sizes, int n_in,
                              void* d_out, int out_size) {
    const int*   uids     = (const int*)d_in[0];
    const int*   pos      = (const int*)d_in[1];
    const int*   neg      = (const int*)d_in[2];
    const int*   adj_rows = (const int*)d_in[3];
    const int*   adj_cols = (const int*)d_in[4];
    const float* adj_vals = (const float*)d_in[5];
    const float* E_u_0    = (const float*)d_in[6];
    const float* E_i_0    = (const float*)d_in[7];
    const float* u_mul_s  = (const float*)d_in[8];
    const float* vt       = (const float*)d_in[9];
    const float* v_mul_s  = (const float*)d_in[10];
    const float* ut       = (const float*)d_in[11];
    const float* W_api    = (const float*)d_in[12];
    const float* b_api    = (const float*)d_in[13];
    const float* W_mashup = (const float*)d_in[14];
    const float* b_mashup = (const float*)d_in[15];
    const float* pos_api  = (const float*)d_in[16];
    const float* neg_api  = (const float*)d_in[17];
    const float* mashup   = (const float*)d_in[18];
    const int*   unpop    = (const int*)d_in[19];
    const int*   popi     = (const int*)d_in[20];

    float* out = (float*)d_out;
    const size_t EMB = (size_t)512 * 768;
    float* out_mashup = out + 3;
    float* out_posapi = out + 3 + EMB;
    float* out_negapi = out + 3 + 2 * EMB;
    float* Eu_out = out + 3 + 3 * EMB;   // Ei_out contiguous after

    float *Zb, *Efb, *Sm, *G;
    cudaGetSymbolAddress((void**)&Zb,  g_Z);
    cudaGetSymbolAddress((void**)&Efb, g_Ef);
    cudaGetSymbolAddress((void**)&Sm,  g_small);
    cudaGetSymbolAddress((void**)&G,   g_G);

    float* Zu1 = Zb;
    float* Zi1 = Zu1 + (size_t)N_U * DD;
    float* Euf = Efb;
    float* Eif = Euf + (size_t)N_U * DD;
    float* Mu = Sm + OFF_MU;
    float* Mi = Sm + OFF_MI;
    float* su = Sm + OFF_SU;
    float* si = Sm + OFF_SI;
    float* sc = Sm + OFF_SC;
    float* Gu = G;
    float* Gi = G + (size_t)BB * DD;

    cudaMemsetAsync(Zb, 0, (size_t)(N_U + N_I) * DD * 4);
    cudaMemsetAsync(Sm, 0, 2304 * 4);

    cudaMemcpyAsync(out_mashup, mashup, EMB * 4, cudaMemcpyDeviceToDevice);
    cudaMemcpyAsync(out_posapi, pos_api, EMB * 4, cudaMemcpyDeviceToDevice);
    cudaMemcpyAsync(out_negapi, neg_api, EMB * 4, cudaMemcpyDeviceToDevice);

    const int spmm_blocks = 2 * (((NNZ_E / 4) * 16 + 255) / 256);
    spmm_dual<<<spmm_blocks, 256>>>(adj_vals, adj_rows, adj_cols,
                                    E_u_0, E_i_0, Zu1, Zi1);
    prep_kernel<<<2048, 256>>>(E_u_0, Zu1, ut, N_U, Euf, Mi, sc);
    prep_kernel<<<1024, 256>>>(E_i_0, Zi1, vt, N_I, Eif, Mu, sc);
    spmm_dual<<<spmm_blocks, 256>>>(adj_vals, adj_rows, adj_cols,
                                    Zu1, Zi1, Euf, Eif);

    reg_w_kernel<<<64, 256>>>(W_api, b_api, W_mashup, b_mashup, sc);
    gsel_kernel<<<1536, 64>>>(uids, pos, neg, E_u_0, E_i_0,
                              u_mul_s, v_mul_s, Mu, Mi, G);

    cudaFuncSetAttribute(logits_simt,
                         cudaFuncAttributeMaxDynamicSharedMemorySize, SMEM_LG);
    const int ntu = (N_U + 127) / 128;   // 782
    const int nti = (N_I + 127) / 128;   // 391
    logits_simt<<<4 * ntu, 256, SMEM_LG>>>(Gu, 4, Euf, N_U, su);
    logits_simt<<<8 * nti, 256, SMEM_LG>>>(Gi, 8, Eif, N_I, si);

    small_loss_kernel<<<2304, 256>>>(uids, pos, neg, Euf, Eif, Gu, Gi,
                                     unpop, popi, sc);

    const size_t n4 = (size_t)(N_U + N_I) * DD / 4;
    copyout_kernel<<<(int)((n4 + 255) / 256), 256>>>(Efb, Eu_out, n4);

    finalize_kernel<<<1, 512>>>(su, si, sc, out);
}